// round 3
// baseline (speedup 1.0000x reference)
#include <cuda_runtime.h>
#include <cstdint>

// ---------------------------------------------------------------------------
// FidelityLSTM: 2-layer LSTM (B=256, T=256, I=512, H=1024) + linear readout.
//
// Strategy:
//   * Permute all gate weights to interleaved layout p = 4*j + g so that a
//     128-wide N-tile of the gate GEMM contains all 4 gates for 32 hidden
//     units -> LSTM cell update fuses into the GEMM epilogue.
//   * Precompute xg = x @ W_ih^T + b for all timesteps (one big GEMM/layer).
//   * 256 sequential step kernels per layer: gates = xg[:,t,:] + h @ W_hh^T,
//     fused cell update, ping-pong h buffers, c updated in place.
//   * All GEMMs: tf32 mma.sync.m16n8k8 with explicit cvt.rna rounding
//     (unbiased) and fp32 accumulation.
// ---------------------------------------------------------------------------

#define BB   256
#define TT   256
#define II   512
#define HH   1024
#define G4H  4096   // 4*H

// ------------------------- scratch (device globals) ------------------------
__device__ float g_xg[(size_t)BB * TT * G4H];    // 268M floats (~1.07 GB)
__device__ float g_hall[(size_t)BB * TT * HH];   // layer-0 hidden sequence
__device__ float g_h[2][BB * HH];                // ping-pong hidden state
__device__ float g_c[BB * HH];                   // cell state
__device__ float g_Wih0p[G4H * II];
__device__ float g_Whh0p[G4H * HH];
__device__ float g_Wih1p[G4H * HH];
__device__ float g_Whh1p[G4H * HH];
__device__ float g_b0p[G4H];
__device__ float g_b1p[G4H];

// ------------------------------ helpers ------------------------------------
__device__ __forceinline__ uint32_t tf32u(float x) {
    uint32_t u;
    asm("cvt.rna.tf32.f32 %0, %1;" : "=r"(u) : "f"(x));
    return u;
}

__device__ __forceinline__ void mma_tf32(float d[4], const uint32_t a[4],
                                         const uint32_t b[2]) {
    asm("mma.sync.aligned.m16n8k8.row.col.f32.tf32.tf32.f32 "
        "{%0,%1,%2,%3}, {%4,%5,%6,%7}, {%8,%9}, {%0,%1,%2,%3};"
        : "+f"(d[0]), "+f"(d[1]), "+f"(d[2]), "+f"(d[3])
        : "r"(a[0]), "r"(a[1]), "r"(a[2]), "r"(a[3]), "r"(b[0]), "r"(b[1]));
}

__device__ __forceinline__ float sigmoidf_(float x) {
    return 1.f / (1.f + __expf(-x));
}

// ---------------------------------------------------------------------------
// Shared GEMM mainloop: C[64 x 128] tile of A[M x K] (row-major, fp32,
// rounded to tf32 at smem fill) times W[N x K] (row-major, pre-rounded tf32)
// i.e. C[m][p] = sum_k A[m][k] * W[p][k].
// 256 threads, warps 2(m) x 4(n), warp tile 32x32, mma m16n8k8.
// smem: As = 64x36 floats, Bs = 128x36 floats (padded, conflict-free frags).
// ---------------------------------------------------------------------------
__device__ __forceinline__ void gemm_tile(
    const float* __restrict__ A, int m0,
    const float* __restrict__ W, int p0, int K,
    float* As, float* Bs, float acc[2][4][4])
{
    const int tid  = threadIdx.x;
    const int lane = tid & 31;
    const int warp = tid >> 5;
    const int wm   = warp >> 2;   // 0..1
    const int wn   = warp & 3;    // 0..3

    for (int k0 = 0; k0 < K; k0 += 32) {
        // ---- fill A tile (64 x 32), convert to tf32 (RNA) ----
        #pragma unroll
        for (int i = 0; i < 2; i++) {
            int idx = tid + i * 256;              // 0..511
            int r   = idx >> 3;                   // 0..63
            int c4  = (idx & 7) << 2;             // 0,4,...,28
            float4 v = *(const float4*)(A + (size_t)(m0 + r) * K + k0 + c4);
            v.x = __uint_as_float(tf32u(v.x));
            v.y = __uint_as_float(tf32u(v.y));
            v.z = __uint_as_float(tf32u(v.z));
            v.w = __uint_as_float(tf32u(v.w));
            *(float4*)(As + r * 36 + c4) = v;
        }
        // ---- fill W tile (128 x 32), already tf32-rounded ----
        #pragma unroll
        for (int i = 0; i < 4; i++) {
            int idx = tid + i * 256;              // 0..1023
            int r   = idx >> 3;                   // 0..127
            int c4  = (idx & 7) << 2;
            *(float4*)(Bs + r * 36 + c4) =
                *(const float4*)(W + (size_t)(p0 + r) * K + k0 + c4);
        }
        __syncthreads();

        // ---- compute: 4 k-steps of 8 ----
        #pragma unroll
        for (int ks = 0; ks < 4; ks++) {
            const int kk = ks * 8 + (lane & 3);
            uint32_t a[2][4];
            #pragma unroll
            for (int mf = 0; mf < 2; mf++) {
                int r = wm * 32 + mf * 16 + (lane >> 2);
                a[mf][0] = __float_as_uint(As[r * 36 + kk]);
                a[mf][1] = __float_as_uint(As[(r + 8) * 36 + kk]);
                a[mf][2] = __float_as_uint(As[r * 36 + kk + 4]);
                a[mf][3] = __float_as_uint(As[(r + 8) * 36 + kk + 4]);
            }
            #pragma unroll
            for (int nf = 0; nf < 4; nf++) {
                int n = wn * 32 + nf * 8 + (lane >> 2);
                uint32_t b[2];
                b[0] = __float_as_uint(Bs[n * 36 + kk]);
                b[1] = __float_as_uint(Bs[n * 36 + kk + 4]);
                mma_tf32(acc[0][nf], a[0], b);
                mma_tf32(acc[1][nf], a[1], b);
            }
        }
        __syncthreads();
    }
}

// ---------------------------------------------------------------------------
// Input GEMM: xg[m][p] = sum_k A[m][k] * W_ih_p[p][k] + bias_p[p]
//   layer 0: A = context [B*T, I]   layer 1: A = g_hall [B*T, H]
// grid: (G4H/128, (B*T)/64) = (32, 1024), 256 threads.
// ---------------------------------------------------------------------------
__global__ void __launch_bounds__(256)
input_gemm_kernel(const float* __restrict__ ctx, int layer)
{
    __shared__ float smem[8448];
    float* As = smem;
    float* Bs = smem + 64 * 36;

    const float* A    = layer ? g_hall  : ctx;
    const float* W    = layer ? g_Wih1p : g_Wih0p;
    const float* bias = layer ? g_b1p   : g_b0p;
    const int K = layer ? HH : II;

    const int m0 = blockIdx.y * 64;
    const int p0 = blockIdx.x * 128;

    float acc[2][4][4];
    #pragma unroll
    for (int i = 0; i < 2; i++)
        #pragma unroll
        for (int j = 0; j < 4; j++)
            #pragma unroll
            for (int l = 0; l < 4; l++) acc[i][j][l] = 0.f;

    gemm_tile(A, m0, W, p0, K, As, Bs, acc);

    const int lane = threadIdx.x & 31;
    const int warp = threadIdx.x >> 5;
    const int wm = warp >> 2, wn = warp & 3;

    #pragma unroll
    for (int mf = 0; mf < 2; mf++) {
        int gm = m0 + wm * 32 + mf * 16 + (lane >> 2);
        #pragma unroll
        for (int nf = 0; nf < 4; nf++) {
            int gp = p0 + wn * 32 + nf * 8 + ((lane & 3) << 1);
            float b0v = bias[gp], b1v = bias[gp + 1];
            size_t base = (size_t)gm * G4H + gp;
            g_xg[base]     = acc[mf][nf][0] + b0v;
            g_xg[base + 1] = acc[mf][nf][1] + b1v;
            size_t base2 = base + (size_t)8 * G4H;
            g_xg[base2]     = acc[mf][nf][2] + b0v;
            g_xg[base2 + 1] = acc[mf][nf][3] + b1v;
        }
    }
}

// ---------------------------------------------------------------------------
// LSTM step: gates = xg[:,t,:] + h_in @ W_hh_p^T, fused cell update.
// grid: (32, 4) CTAs of 256 threads. Tile owns batch rows [m0,m0+64) and
// hidden units [p0/4, p0/4+32) (all 4 gates).
// ---------------------------------------------------------------------------
template <bool STORE_SEQ>
__global__ void __launch_bounds__(256)
lstm_step_kernel(int layer, int t, int hin)
{
    __shared__ float smem[8448];
    float* As = smem;
    float* Bs = smem + 64 * 36;

    const float* W    = layer ? g_Whh1p : g_Whh0p;
    const float* A    = g_h[hin];
    float*       hout = g_h[hin ^ 1];

    const int m0 = blockIdx.y * 64;
    const int p0 = blockIdx.x * 128;

    float acc[2][4][4];
    #pragma unroll
    for (int i = 0; i < 2; i++)
        #pragma unroll
        for (int j = 0; j < 4; j++)
            #pragma unroll
            for (int l = 0; l < 4; l++) acc[i][j][l] = 0.f;

    gemm_tile(A, m0, W, p0, HH, As, Bs, acc);

    const int lane = threadIdx.x & 31;
    const int warp = threadIdx.x >> 5;
    const int wm = warp >> 2, wn = warp & 3;

    // stage gates (+ xg) into smem so each thread can gather i,f,g,o per unit
    float* gs = smem;  // [64][132]
    #pragma unroll
    for (int mf = 0; mf < 2; mf++) {
        int lm = wm * 32 + mf * 16 + (lane >> 2);
        int gb = m0 + lm;
        #pragma unroll
        for (int nf = 0; nf < 4; nf++) {
            int lp = wn * 32 + nf * 8 + ((lane & 3) << 1);
            size_t x0 = ((size_t)gb * TT + t) * G4H + p0 + lp;
            gs[lm * 132 + lp]     = acc[mf][nf][0] + g_xg[x0];
            gs[lm * 132 + lp + 1] = acc[mf][nf][1] + g_xg[x0 + 1];
            size_t x1 = ((size_t)(gb + 8) * TT + t) * G4H + p0 + lp;
            gs[(lm + 8) * 132 + lp]     = acc[mf][nf][2] + g_xg[x1];
            gs[(lm + 8) * 132 + lp + 1] = acc[mf][nf][3] + g_xg[x1 + 1];
        }
    }
    __syncthreads();

    const int j0 = p0 >> 2;  // first hidden unit of this tile
    #pragma unroll
    for (int it = threadIdx.x; it < 64 * 32; it += 256) {
        int lm = it >> 5;      // local batch row 0..63
        int lj = it & 31;      // local hidden unit 0..31
        float4 gv = *(float4*)(gs + lm * 132 + (lj << 2));
        int b = m0 + lm;
        int j = j0 + lj;
        float ig = sigmoidf_(gv.x);
        float fg = sigmoidf_(gv.y);
        float gg = tanhf(gv.z);
        float og = sigmoidf_(gv.w);
        int hc = b * HH + j;
        float c = fg * g_c[hc] + ig * gg;
        g_c[hc] = c;
        float h = og * tanhf(c);
        hout[hc] = h;
        if (STORE_SEQ)
            g_hall[((size_t)b * TT + t) * HH + j] = h;
    }
}

// ---------------------------------------------------------------------------
// Weight permutation: dst[p][k] = tf32_round(src[g*H + j][k]), p = 4j + g.
// ---------------------------------------------------------------------------
__global__ void permute_kernel(const float* __restrict__ src, int sel, int K)
{
    float* dst = (sel == 0) ? g_Wih0p : (sel == 1) ? g_Whh0p
               : (sel == 2) ? g_Wih1p : g_Whh1p;
    size_t n = (size_t)G4H * K;
    for (size_t idx = (size_t)blockIdx.x * blockDim.x + threadIdx.x; idx < n;
         idx += (size_t)gridDim.x * blockDim.x) {
        int p = (int)(idx / K);
        int k = (int)(idx % K);
        int j = p >> 2, g = p & 3;
        dst[idx] = __uint_as_float(tf32u(src[(size_t)(g * HH + j) * K + k]));
    }
}

__global__ void bias_kernel(const float* __restrict__ bih,
                            const float* __restrict__ bhh, int layer)
{
    int p = blockIdx.x * blockDim.x + threadIdx.x;
    if (p < G4H) {
        int j = p >> 2, g = p & 3;
        int r = g * HH + j;
        (layer ? g_b1p : g_b0p)[p] = bih[r] + bhh[r];
    }
}

__global__ void init_hc_kernel(const float* __restrict__ init_hidden)
{
    int i = blockIdx.x * blockDim.x + threadIdx.x;
    if (i < BB * HH) {
        g_h[0][i] = init_hidden[i];
        g_c[i] = 0.f;
    }
}

// readout: out[b] = h_final[b] . W_ro + b_ro   (fp32)
__global__ void readout_kernel(const float* __restrict__ Wro,
                               const float* __restrict__ bro,
                               float* __restrict__ out)
{
    int b = blockIdx.x;
    const float* h = g_h[0] + b * HH;
    float s = 0.f;
    for (int j = threadIdx.x; j < HH; j += 128) s += h[j] * Wro[j];
    #pragma unroll
    for (int o = 16; o; o >>= 1) s += __shfl_down_sync(0xffffffff, s, o);
    __shared__ float red[4];
    if ((threadIdx.x & 31) == 0) red[threadIdx.x >> 5] = s;
    __syncthreads();
    if (threadIdx.x == 0)
        out[b] = red[0] + red[1] + red[2] + red[3] + bro[0];
}

// ---------------------------------------------------------------------------
extern "C" void kernel_launch(void* const* d_in, const int* in_sizes, int n_in,
                              void* d_out, int out_size)
{
    const float* init_hidden = (const float*)d_in[0];
    const float* context     = (const float*)d_in[1];
    const float* W_ih0       = (const float*)d_in[2];
    const float* W_hh0       = (const float*)d_in[3];
    const float* b_ih0       = (const float*)d_in[4];
    const float* b_hh0       = (const float*)d_in[5];
    const float* W_ih1       = (const float*)d_in[6];
    const float* W_hh1       = (const float*)d_in[7];
    const float* b_ih1       = (const float*)d_in[8];
    const float* b_hh1       = (const float*)d_in[9];
    const float* W_ro        = (const float*)d_in[10];
    const float* b_ro        = (const float*)d_in[11];
    float* out = (float*)d_out;

    // weight/bias preprocessing (tf32-rounded, gate-interleaved)
    permute_kernel<<<2048, 256>>>(W_ih0, 0, II);
    permute_kernel<<<2048, 256>>>(W_hh0, 1, HH);
    permute_kernel<<<2048, 256>>>(W_ih1, 2, HH);
    permute_kernel<<<2048, 256>>>(W_hh1, 3, HH);
    bias_kernel<<<(G4H + 255) / 256, 256>>>(b_ih0, b_hh0, 0);
    bias_kernel<<<(G4H + 255) / 256, 256>>>(b_ih1, b_hh1, 1);

    const dim3 blk(256);
    const dim3 g_in(G4H / 128, (BB * TT) / 64);  // (32, 1024)
    const dim3 g_st(G4H / 128, BB / 64);         // (32, 4)
    const int  ginit = (BB * HH + 255) / 256;

    // ---- layer 0 ----
    input_gemm_kernel<<<g_in, blk>>>(context, 0);
    init_hc_kernel<<<ginit, 256>>>(init_hidden);
    for (int t = 0; t < TT; t++)
        lstm_step_kernel<true><<<g_st, blk>>>(0, t, t & 1);

    // ---- layer 1 ----
    input_gemm_kernel<<<g_in, blk>>>(nullptr, 1);
    init_hc_kernel<<<ginit, 256>>>(init_hidden);
    for (int t = 0; t < TT; t++)
        lstm_step_kernel<false><<<g_st, blk>>>(1, t, t & 1);

    // ---- readout ----
    readout_kernel<<<BB, 128>>>(W_ro, b_ro, out);
}